// round 5
// baseline (speedup 1.0000x reference)
#include <cuda_runtime.h>

#define B_    16
#define TQ_   128
#define TK_   128
#define EMB_  256
#define HID_  100
#define F2E_  512   // 2*EMB

// Scratch (allocation-free rule: __device__ globals)
__device__ float g_A[B_ * TK_ * HID_];        // A[b][i][h]
__device__ float g_Ct[B_ * HID_ * TQ_];       // C^T[b][h][j]  (includes +b1)
__device__ float g_feat[B_ * TK_ * F2E_];     // [row][f]  f<256: mul, f>=256: sub^2

__device__ __forceinline__ float ftanh(float x) {
    float y;
    asm("tanh.approx.f32 %0, %1;" : "=f"(y) : "f"(x));
    return y;
}

#define XSTR 36   // smem stride for 32-wide tiles
#define WSTR 68   // smem stride for 64-wide tiles

// ---------------------------------------------------------------------------
// K1: prep GEMM over fused M=4096 (rows 0..2047: keys -> A with W1[:, :256];
//     rows 2048..4095: queries -> Ct with W1[:, 256:] + b1).
// BM=32, BN=64, BK=32, 256 threads, 2x4 micro, double-buffered.
// grid (2, 128) = 256 blocks, 8 warps each -> ~14 warps/SM.
// ---------------------------------------------------------------------------
__global__ void __launch_bounds__(256) prep_gemm(
        const float* __restrict__ queries,
        const float* __restrict__ keys,
        const float* __restrict__ W1,
        const float* __restrict__ b1) {
    __shared__ __align__(16) float Xs[2][32 * XSTR];
    __shared__ __align__(16) float Ws[2][32 * WSTR];

    int m0g = blockIdx.y * 32;
    int side = m0g >= (B_ * TK_);
    int m0 = m0g & (B_ * TK_ - 1);
    int n0 = blockIdx.x * 64;
    const float* X  = side ? queries : keys;
    const float* Wb = W1 + (side ? EMB_ : 0);

    int tid = threadIdx.x;
    int lc = tid & 31, lr = tid >> 5;      // k-lane, row group (0..7)
    int tx = tid & 15, ty = tid >> 4;      // micro col (4), micro row pair (0..15)

    float acc[8];
    #pragma unroll
    for (int i = 0; i < 8; ++i) acc[i] = 0.f;

    float rx[4], rw[8];
    #pragma unroll
    for (int u = 0; u < 4; ++u)
        rx[u] = X[(m0 + lr + 8 * u) * EMB_ + lc];
    #pragma unroll
    for (int u = 0; u < 8; ++u) {
        int h = n0 + lr + 8 * u;
        rw[u] = (h < HID_) ? Wb[h * F2E_ + lc] : 0.f;
    }
    #pragma unroll
    for (int u = 0; u < 4; ++u)
        Xs[0][lc * XSTR + lr + 8 * u] = rx[u];
    #pragma unroll
    for (int u = 0; u < 8; ++u)
        Ws[0][lc * WSTR + lr + 8 * u] = rw[u];
    __syncthreads();

    const int NT = EMB_ / 32;  // 8
    #pragma unroll 1
    for (int t = 0; t < NT; ++t) {
        if (t + 1 < NT) {
            int k0 = (t + 1) * 32;
            #pragma unroll
            for (int u = 0; u < 4; ++u)
                rx[u] = X[(m0 + lr + 8 * u) * EMB_ + k0 + lc];
            #pragma unroll
            for (int u = 0; u < 8; ++u) {
                int h = n0 + lr + 8 * u;
                rw[u] = (h < HID_) ? Wb[h * F2E_ + k0 + lc] : 0.f;
            }
        }
        const float* Xb = Xs[t & 1];
        const float* Bb = Ws[t & 1];
        #pragma unroll
        for (int k = 0; k < 32; ++k) {
            float2 xv = *(const float2*)&Xb[k * XSTR + ty * 2];
            float4 wv = *(const float4*)&Bb[k * WSTR + tx * 4];
            acc[0] = fmaf(xv.x, wv.x, acc[0]);
            acc[1] = fmaf(xv.x, wv.y, acc[1]);
            acc[2] = fmaf(xv.x, wv.z, acc[2]);
            acc[3] = fmaf(xv.x, wv.w, acc[3]);
            acc[4] = fmaf(xv.y, wv.x, acc[4]);
            acc[5] = fmaf(xv.y, wv.y, acc[5]);
            acc[6] = fmaf(xv.y, wv.z, acc[6]);
            acc[7] = fmaf(xv.y, wv.w, acc[7]);
        }
        if (t + 1 < NT) {
            int nb = (t + 1) & 1;
            #pragma unroll
            for (int u = 0; u < 4; ++u)
                Xs[nb][lc * XSTR + lr + 8 * u] = rx[u];
            #pragma unroll
            for (int u = 0; u < 8; ++u)
                Ws[nb][lc * WSTR + lr + 8 * u] = rw[u];
            __syncthreads();
        }
    }

    #pragma unroll
    for (int i = 0; i < 2; ++i) {
        int row = m0 + ty * 2 + i;
        #pragma unroll
        for (int q = 0; q < 4; ++q) {
            int h = n0 + tx * 4 + q;
            if (h < HID_) {
                if (side == 0) {
                    g_A[row * HID_ + h] = acc[i * 4 + q];
                } else {
                    int b = row >> 7, j = row & 127;
                    g_Ct[(b * HID_ + h) * TQ_ + j] = acc[i * 4 + q] + b1[h];
                }
            }
        }
    }
}

// ---------------------------------------------------------------------------
// K2: fused score MLP + softmax + attention + feature build.
// One block per (b, 4-row i-tile): grid (32, 16) = 512 blocks, 256 threads.
// ---------------------------------------------------------------------------
#define ITILE 4
#define PSTR  8

__global__ void __launch_bounds__(256) attn_kernel(
        const float* __restrict__ queries,
        const float* __restrict__ keys,
        const float* __restrict__ qmask,
        const float* __restrict__ kmask,
        const float* __restrict__ W2) {
    extern __shared__ __align__(16) float sm[];
    float* c_s  = sm;                        // 12800
    float* a_s  = c_s + HID_ * TQ_;          // 400
    float* p_s  = a_s + ITILE * HID_;        // 128*8 = 1024
    float* w2_s = p_s + TQ_ * PSTR;          // 104
    float* km_s = w2_s + 104;                // 4

    int b  = blockIdx.y;
    int i0 = blockIdx.x * ITILE;
    int tid = threadIdx.x;

    {   // vectorized c_s load (g_Ct rows are contiguous per batch)
        const float4* src = (const float4*)(g_Ct + b * HID_ * TQ_);
        float4* dst = (float4*)c_s;
        for (int idx = tid; idx < (HID_ * TQ_) / 4; idx += 256)
            dst[idx] = src[idx];
    }
    for (int idx = tid; idx < ITILE * HID_; idx += 256)
        a_s[idx] = g_A[(b * TK_ + i0) * HID_ + idx];
    if (tid < HID_)  w2_s[tid] = W2[tid];
    if (tid < ITILE) km_s[tid] = kmask[b * TK_ + i0 + tid];

    int j = tid & 127;        // query position
    int g = tid >> 7;         // i-row parity (0/1)
    float qm = qmask[b * TQ_ + j];
    __syncthreads();

    // ---- phase 1: sim[ii][j] = sum_h tanh(a[ii,h] + c[h,j]) * w2[h]
    float acc0 = 0.f, acc1 = 0.f;
    for (int h = 0; h < HID_; ++h) {
        float cj = c_s[h * TQ_ + j];
        float w  = w2_s[h];
        float x0 = a_s[g * HID_ + h] + cj;
        float x1 = a_s[(g + 2) * HID_ + h] + cj;
        acc0 = fmaf(w, ftanh(x0), acc0);
        acc1 = fmaf(w, ftanh(x1), acc1);
    }
    const float NEGC = -4294967295.0f;  // -2^32 + 1
    p_s[j * PSTR + g]     = (qm == 0.0f) ? NEGC : acc0;
    p_s[j * PSTR + g + 2] = (qm == 0.0f) ? NEGC : acc1;
    __syncthreads();

    // ---- phase 2: softmax over j; warps 0..3 own rows 0..3
    int warp = tid >> 5, lane = tid & 31;
    if (warp < ITILE) {
        int ii = warp;
        float v[4];
        float m = -3.4e38f;
        #pragma unroll
        for (int q = 0; q < 4; ++q) {
            v[q] = p_s[(lane + 32 * q) * PSTR + ii];
            m = fmaxf(m, v[q]);
        }
        #pragma unroll
        for (int off = 16; off; off >>= 1)
            m = fmaxf(m, __shfl_xor_sync(0xffffffffu, m, off));
        float ssum = 0.f;
        #pragma unroll
        for (int q = 0; q < 4; ++q) { v[q] = __expf(v[q] - m); ssum += v[q]; }
        #pragma unroll
        for (int off = 16; off; off >>= 1)
            ssum += __shfl_xor_sync(0xffffffffu, ssum, off);
        float scale = km_s[ii] / ssum;   // fold key_mask scalar into p
        #pragma unroll
        for (int q = 0; q < 4; ++q)
            p_s[(lane + 32 * q) * PSTR + ii] = v[q] * scale;
    }
    __syncthreads();

    // ---- phase 3: keys_attn[ii,e] = sum_j p[ii,j] * q[b,j,e]; then features
    int e = tid;  // 0..255
    float ka[ITILE];
    #pragma unroll
    for (int r = 0; r < ITILE; ++r) ka[r] = 0.f;
    const float* qb = queries + b * TQ_ * EMB_ + e;
    #pragma unroll 4
    for (int jj = 0; jj < TQ_; ++jj) {
        float qv = qb[jj * EMB_];
        float4 pv = *(const float4*)&p_s[jj * PSTR];
        ka[0] = fmaf(pv.x, qv, ka[0]);
        ka[1] = fmaf(pv.y, qv, ka[1]);
        ka[2] = fmaf(pv.z, qv, ka[2]);
        ka[3] = fmaf(pv.w, qv, ka[3]);
    }
    #pragma unroll
    for (int r = 0; r < ITILE; ++r) {
        int rowg = b * TK_ + i0 + r;
        float kv = keys[rowg * EMB_ + e];
        float fm = ka[r] * kv;
        float d  = ka[r] - kv;
        g_feat[rowg * F2E_ + e]        = fm;
        g_feat[rowg * F2E_ + EMB_ + e] = d * d;
    }
}

// ---------------------------------------------------------------------------
// K3: out[2048,256] = relu(feat[2048,512] @ Wlast[256,512]^T + blast)
// BM=32, BN=64, BK=32, 256 threads, 2x4 micro, double-buffered.
// grid (4, 64) = 256 blocks.
// ---------------------------------------------------------------------------
__global__ void __launch_bounds__(256) gemm_kernel(
        const float* __restrict__ Wlast,
        const float* __restrict__ blast,
        float* __restrict__ out) {
    __shared__ __align__(16) float As[2][32 * XSTR];
    __shared__ __align__(16) float Bs[2][32 * WSTR];

    int m0 = blockIdx.y * 32;
    int n0 = blockIdx.x * 64;
    int tid = threadIdx.x;
    int lc = tid & 31, lr = tid >> 5;
    int tx = tid & 15, ty = tid >> 4;

    float acc[8];
    #pragma unroll
    for (int i = 0; i < 8; ++i) acc[i] = 0.f;

    float ra[4], rb[8];
    #pragma unroll
    for (int u = 0; u < 4; ++u)
        ra[u] = g_feat[(m0 + lr + 8 * u) * F2E_ + lc];
    #pragma unroll
    for (int u = 0; u < 8; ++u)
        rb[u] = Wlast[(n0 + lr + 8 * u) * F2E_ + lc];
    #pragma unroll
    for (int u = 0; u < 4; ++u)
        As[0][lc * XSTR + lr + 8 * u] = ra[u];
    #pragma unroll
    for (int u = 0; u < 8; ++u)
        Bs[0][lc * WSTR + lr + 8 * u] = rb[u];
    __syncthreads();

    const int NT = F2E_ / 32;  // 16
    #pragma unroll 1
    for (int t = 0; t < NT; ++t) {
        if (t + 1 < NT) {
            int k0 = (t + 1) * 32;
            #pragma unroll
            for (int u = 0; u < 4; ++u)
                ra[u] = g_feat[(m0 + lr + 8 * u) * F2E_ + k0 + lc];
            #pragma unroll
            for (int u = 0; u < 8; ++u)
                rb[u] = Wlast[(n0 + lr + 8 * u) * F2E_ + k0 + lc];
        }
        const float* Ab = As[t & 1];
        const float* Bb = Bs[t & 1];
        #pragma unroll
        for (int k = 0; k < 32; ++k) {
            float2 av = *(const float2*)&Ab[k * XSTR + ty * 2];
            float4 bv = *(const float4*)&Bb[k * WSTR + tx * 4];
            acc[0] = fmaf(av.x, bv.x, acc[0]);
            acc[1] = fmaf(av.x, bv.y, acc[1]);
            acc[2] = fmaf(av.x, bv.z, acc[2]);
            acc[3] = fmaf(av.x, bv.w, acc[3]);
            acc[4] = fmaf(av.y, bv.x, acc[4]);
            acc[5] = fmaf(av.y, bv.y, acc[5]);
            acc[6] = fmaf(av.y, bv.z, acc[6]);
            acc[7] = fmaf(av.y, bv.w, acc[7]);
        }
        if (t + 1 < NT) {
            int nb = (t + 1) & 1;
            #pragma unroll
            for (int u = 0; u < 4; ++u)
                As[nb][lc * XSTR + lr + 8 * u] = ra[u];
            #pragma unroll
            for (int u = 0; u < 8; ++u)
                Bs[nb][lc * WSTR + lr + 8 * u] = rb[u];
            __syncthreads();
        }
    }

    float4 bb = *(const float4*)&blast[n0 + tx * 4];
    #pragma unroll
    for (int i = 0; i < 2; ++i) {
        int row = m0 + ty * 2 + i;
        float4 o;
        o.x = fmaxf(acc[i * 4 + 0] + bb.x, 0.f);
        o.y = fmaxf(acc[i * 4 + 1] + bb.y, 0.f);
        o.z = fmaxf(acc[i * 4 + 2] + bb.z, 0.f);
        o.w = fmaxf(acc[i * 4 + 3] + bb.w, 0.f);
        *(float4*)&out[row * EMB_ + n0 + tx * 4] = o;
    }
}

// ---------------------------------------------------------------------------
extern "C" void kernel_launch(void* const* d_in, const int* in_sizes, int n_in,
                              void* d_out, int out_size) {
    const float* queries = (const float*)d_in[0];
    const float* keys    = (const float*)d_in[1];
    const float* qmask   = (const float*)d_in[2];
    const float* kmask   = (const float*)d_in[3];
    const float* W1      = (const float*)d_in[4];
    const float* b1      = (const float*)d_in[5];
    const float* W2      = (const float*)d_in[6];
    const float* Wlast   = (const float*)d_in[7];
    const float* blast   = (const float*)d_in[8];
    float* out = (float*)d_out;

    const int smem_attn = (HID_ * TQ_ + ITILE * HID_ + TQ_ * PSTR + 104 + ITILE) * 4;
    cudaFuncSetAttribute(attn_kernel, cudaFuncAttributeMaxDynamicSharedMemorySize,
                         smem_attn);

    prep_gemm<<<dim3(2, (2 * B_ * TK_) / 32), 256>>>(queries, keys, W1, b1);
    attn_kernel<<<dim3(TK_ / ITILE, B_), 256, smem_attn>>>(queries, keys, qmask,
                                                           kmask, W2);
    gemm_kernel<<<dim3(EMB_ / 64, (B_ * TK_) / 32), 256>>>(Wlast, blast, out);
}